// round 15
// baseline (speedup 1.0000x reference)
#include <cuda_runtime.h>
#include <cuda_bf16.h>
#include <math.h>

// ---------------------------------------------------------------------------
// CombinedLoss via mma.sync m16n8k16 bf16. CWT(o)-CWT(t) = CWT(d); 36 morlet
// kernels padded into one 360-tap window; per 128-output tile:
// D[128x40] = A[128x384]*B[40x384]^T, A Hankel, B-frags constexpr,
// per-n-tile K-trimming (78/120 fragment pairs).
// Round 15: 256 threads / 8 warps per CTA, each warp owns an m16 slice ->
// 2x warps per SMSP for latency hiding, half the per-warp HMMA chain.
// ---------------------------------------------------------------------------

#define L_TOTAL 262144
#define THREADS 256
#define MTILE   128
#define TILES   (L_TOTAL / MTILE)   // 2048
#define TPC     2
#define GRID    (TILES / TPC)       // 1024
#define NW      36
#define NTB     5
#define KSTEPS  24
#define WINF    516
#define NFRAG   78
#define BF_U32  (NFRAG * 64)        // 19968 B

__device__ float g_cwt_part[GRID];
__device__ float g_wave_part[GRID];
__device__ unsigned g_done;

__host__ __device__ constexpr int NMIN[KSTEPS] =
    {4,3,3,2,2,2,1,1,0,0,0,0,0,0,1,1,1,2,2,3,3,3,4,4};
__host__ __device__ constexpr int FOFF[KSTEPS] =
    {0,1,3,5,8,11,14,18,22,27,32,37,42,47,52,56,60,64,67,70,72,74,76,77};

// ======================= constexpr morlet coefficients ======================
__host__ __device__ constexpr double cabs_(double v) { return v < 0.0 ? -v : v; }

__host__ __device__ constexpr double cexp_(double xx) {
    if (xx < -120.0) return 0.0;
    const double LN2_HI = 6.93147180369123816490e-01;
    const double LN2_LO = 1.90821492927058770002e-10;
    const double INV_LN2 = 1.44269504088896338700e+00;
    double nd = xx * INV_LN2;
    int n = (int)(nd >= 0.0 ? nd + 0.5 : nd - 0.5);
    double r = (xx - (double)n * LN2_HI) - (double)n * LN2_LO;
    double term = 1.0, sum = 1.0;
    for (int i = 1; i <= 18; ++i) {
        term *= r / (double)i;
        sum += term;
        if (cabs_(term) < 1e-60) break;
    }
    double p = 1.0, b = (n < 0) ? 0.5 : 2.0;
    int m = (n < 0) ? -n : n;
    while (m) { if (m & 1) p *= b; m >>= 1; if (m) b *= b; }
    return sum * p;
}
__host__ __device__ constexpr double ccos_(double xx) {
    const double PIO2_1  = 1.57079632673412561417e+00;
    const double PIO2_1t = 6.07710050650619224932e-11;
    double ax = xx < 0.0 ? -xx : xx;
    int q = (int)(ax * 0.63661977236758134308 + 0.5);
    double r = (ax - (double)q * PIO2_1) - (double)q * PIO2_1t;
    double r2 = r * r;
    double cs = 1.0, tc = 1.0;
    for (int i = 1; i <= 10; ++i) {
        tc *= -r2 / (double)((2 * i - 1) * (2 * i));
        cs += tc;
        if (cabs_(tc) < 1e-60) break;
    }
    double sn = r, ts = r;
    for (int i = 1; i <= 10; ++i) {
        ts *= -r2 / (double)((2 * i) * (2 * i + 1));
        sn += ts;
        if (cabs_(ts) < 1e-60) break;
    }
    int quad = q & 3;
    return quad == 0 ? cs : quad == 1 ? -sn : quad == 2 ? -cs : sn;
}
__host__ __device__ constexpr double morlet_tap(int w, int p) {
    const double TWO_PI = 6.28318530717958647692;
    const double PI_M025 = 0.75112554446494248286;
    int N = 10 * w;
    double step = (2.0 * TWO_PI) / (double)(N - 1);
    double x = -TWO_PI + (double)p * step;
    double ew = cexp_(-0.5 * (double)(w * w));
    return (ccos_((double)w * x) - ew) * cexp_(-0.5 * x * x) * PI_M025;
}

__host__ __device__ constexpr unsigned short f2bf(double dv) {
    if (dv == 0.0) return 0;
    unsigned s = dv < 0.0 ? 1u : 0u;
    double x = s ? -dv : dv;
    int e = 127;
    while (x >= 2.0) { x *= 0.5; ++e; }
    while (x < 1.0)  { x *= 2.0; --e; }
    double mf = (x - 1.0) * 128.0;
    int m = (int)mf;
    double rem = mf - (double)m;
    if (rem > 0.5 || (rem == 0.5 && (m & 1))) ++m;
    if (m == 128) { m = 0; ++e; }
    if (e <= 0 || e >= 255) return (unsigned short)(s << 15);
    return (unsigned short)((s << 15) | ((unsigned)e << 7) | (unsigned)m);
}

__host__ __device__ constexpr double khat(int n, int p) {
    if (n >= NW) return 0.0;
    int w = n + 1;
    int q = p - 180 + 5 * w;
    if (q < 0 || q >= 10 * w) return 0.0;
    return morlet_tap(w, q);
}

struct BFt { unsigned v[BF_U32]; };
__host__ __device__ constexpr BFt make_bf() {
    BFt t{};
    for (int ks = 0; ks < KSTEPS; ++ks)
        for (int nt = NMIN[ks]; nt < NTB; ++nt) {
            int fi = FOFF[ks] + nt - NMIN[ks];
            for (int ln = 0; ln < 32; ++ln)
                for (int rg = 0; rg < 2; ++rg) {
                    int n  = nt * 8 + ln / 4;
                    int k0 = 16 * ks + (ln % 4) * 2 + rg * 8;
                    unsigned lo = f2bf(khat(n, k0));
                    unsigned hi = f2bf(khat(n, k0 + 1));
                    t.v[(fi * 32 + ln) * 2 + rg] = lo | (hi << 16);
                }
        }
    return t;
}
__device__ __align__(16) const BFt g_bf = make_bf();

// ============================ helpers =======================================
__device__ __forceinline__ void mma_bf16(float* d, unsigned a0, unsigned a1,
                                         unsigned a2, unsigned a3,
                                         unsigned b0, unsigned b1) {
    asm volatile(
        "mma.sync.aligned.m16n8k16.row.col.f32.bf16.bf16.f32 "
        "{%0,%1,%2,%3}, {%4,%5,%6,%7}, {%8,%9}, {%0,%1,%2,%3};"
        : "+f"(d[0]), "+f"(d[1]), "+f"(d[2]), "+f"(d[3])
        : "r"(a0), "r"(a1), "r"(a2), "r"(a3), "r"(b0), "r"(b1));
}

__device__ __forceinline__ float warp_sum(float v) {
    #pragma unroll
    for (int o = 16; o > 0; o >>= 1) v += __shfl_xor_sync(0xFFFFFFFFu, v, o);
    return v;
}

// ---------------------------------------------------------------------------
__global__ void __launch_bounds__(THREADS, 4)
cwt_mma_kernel(const float* __restrict__ o, const float* __restrict__ t,
               float* __restrict__ out) {
    __shared__ __align__(16) unsigned sBF[BF_U32];
    __shared__ __align__(16) unsigned sWI[512];
    __shared__ __align__(8) float sWin[WINF];
    __shared__ float s_red[16];
    __shared__ unsigned s_last;
    __shared__ double s_fin[2 * THREADS];

    const int tid  = threadIdx.x;
    const int wid  = tid >> 5;              // 0..7
    const int lane = tid & 31;
    const int mbase = wid * 16;             // each warp: m16 slice

    // Compact B fragment table -> smem (once per CTA)
    {
        const uint4* src = reinterpret_cast<const uint4*>(g_bf.v);
        uint4* dst = reinterpret_cast<uint4*>(sBF);
        for (int i = tid; i < BF_U32 / 4; i += THREADS) dst[i] = src[i];
    }

    float csum = 0.f, wsum = 0.f;

    #pragma unroll 1
    for (int it = 0; it < TPC; ++it) {
        const int tile0 = (blockIdx.x * TPC + it) * MTILE;
        __syncthreads();

        // fp32 diff window, zero outside [0,L): sWin[j] = d(tile0 + j - 180)
        for (int j = tid; j < WINF; j += THREADS) {
            int g = tile0 - 180 + j;
            float v = 0.f;
            if (j < 512 && g >= 0 && g < L_TOTAL) v = o[g] - t[g];
            sWin[j] = v;
        }
        __syncthreads();
        // packed bf16 pairs WI[j] = (d_j, d_{j+1}); fp32 wave |d| term
        for (int j = tid; j < 512; j += THREADS) {
            unsigned lo = (unsigned)__bfloat16_as_ushort(__float2bfloat16(sWin[j]));
            unsigned hi = (unsigned)__bfloat16_as_ushort(__float2bfloat16(sWin[j + 1]));
            sWI[j] = lo | (hi << 16);
        }
        if (tid < 128) wsum += fabsf(sWin[180 + tid]);
        __syncthreads();

        float acc[NTB][4];
        #pragma unroll
        for (int nt = 0; nt < NTB; ++nt)
            #pragma unroll
            for (int r = 0; r < 4; ++r) acc[nt][r] = 0.f;

        // Fully unrolled: per ks, only active n-tiles (78 HMMAs per warp/tile)
        #pragma unroll
        for (int ks = 0; ks < KSTEPS; ++ks) {
            const int bj = mbase + (lane >> 2) + 16 * ks + 2 * (lane & 3);
            unsigned p0 = sWI[bj];
            unsigned p1 = sWI[bj + 8];      // row+8 == col+8 (Hankel)
            unsigned p2 = sWI[bj + 16];
            #pragma unroll
            for (int nt = 0; nt < NTB; ++nt) {
                if (nt >= NMIN[ks]) {       // compile-time after unroll
                    const int fi = FOFF[ks] + nt - NMIN[ks];
                    uint2 b = *reinterpret_cast<const uint2*>(&sBF[fi * 64 + lane * 2]);
                    mma_bf16(acc[nt], p0, p1, p1, p2, b.x, b.y);
                }
            }
        }

        // |D| epilogue. Cols n = nt*8 + 2*(lane&3) + {0,1}; drop n >= 36.
        #pragma unroll
        for (int nt = 0; nt < 4; ++nt)
            #pragma unroll
            for (int r = 0; r < 4; ++r) csum += fabsf(acc[nt][r]);
        if ((lane & 3) < 2)
            #pragma unroll
            for (int r = 0; r < 4; ++r) csum += fabsf(acc[4][r]);
    }

    // Block reduction -> per-block partials
    csum = warp_sum(csum);
    wsum = warp_sum(wsum);
    if (lane == 0) { s_red[wid] = csum; s_red[8 + wid] = wsum; }
    __syncthreads();
    if (tid == 0) {
        float c = 0.f, w = 0.f;
        #pragma unroll
        for (int i = 0; i < 8; ++i) { c += s_red[i]; w += s_red[8 + i]; }
        g_cwt_part[blockIdx.x]  = c;
        g_wave_part[blockIdx.x] = w;
    }

    // Last block finalizes
    __threadfence();
    if (tid == 0) {
        unsigned old = atomicAdd(&g_done, 1u);
        s_last = (old == GRID - 1) ? 1u : 0u;
    }
    __syncthreads();
    if (s_last) {
        double sc = 0.0, sw = 0.0;
        for (int i = tid; i < GRID; i += THREADS) {
            sc += (double)__ldcg(&g_cwt_part[i]);
            sw += (double)__ldcg(&g_wave_part[i]);
        }
        s_fin[tid] = sc; s_fin[THREADS + tid] = sw;
        __syncthreads();
        #pragma unroll
        for (int s = THREADS / 2; s > 0; s >>= 1) {
            if (tid < s) {
                s_fin[tid] += s_fin[tid + s];
                s_fin[THREADS + tid] += s_fin[THREADS + tid + s];
            }
            __syncthreads();
        }
        if (tid == 0) {
            double lw = s_fin[THREADS] / (double)L_TOTAL;
            double lc = s_fin[0] / (36.0 * (double)L_TOTAL);
            out[0] = (float)(0.5 * lw + 0.5 * lc);
            g_done = 0;                     // reset for next replay
        }
    }
}

extern "C" void kernel_launch(void* const* d_in, const int* in_sizes, int n_in,
                              void* d_out, int out_size) {
    const float* o = (const float*)d_in[0];
    const float* t = (const float*)d_in[1];
    float* out = (float*)d_out;

    cwt_mma_kernel<<<GRID, THREADS>>>(o, t, out);
}

// round 16
// speedup vs baseline: 1.1634x; 1.1634x over previous
#include <cuda_runtime.h>
#include <cuda_bf16.h>
#include <math.h>

// ---------------------------------------------------------------------------
// CombinedLoss via mma.sync m16n8k16 bf16. CWT(o)-CWT(t) = CWT(d); 36 morlet
// kernels padded into one 360-tap window; D = A_hankel * B^T per tile.
// Round 16: 256-output supertile per CTA, 8 warps x m32 each ->
// B-fragment LDS reused across 2 HMMAs (R13 ratio) at 8-warp occupancy (R15),
// 2 independent HMMA chains per warp, single sync per CTA.
// ---------------------------------------------------------------------------

#define L_TOTAL 262144
#define THREADS 256
#define STILE   256                 // outputs per CTA
#define GRID    (L_TOTAL / STILE)   // 1024
#define NW      36
#define NTB     5
#define KSTEPS  24
#define WIN_V   616                 // 256 + 360 valid window entries
#define WIN_A   640                 // padded (max a-index 637)
#define NFRAG   78
#define BF_U32  (NFRAG * 64)        // 19968 B

__device__ float g_cwt_part[GRID];
__device__ float g_wave_part[GRID];
__device__ unsigned g_done;

__host__ __device__ constexpr int NMIN[KSTEPS] =
    {4,3,3,2,2,2,1,1,0,0,0,0,0,0,1,1,1,2,2,3,3,3,4,4};
__host__ __device__ constexpr int FOFF[KSTEPS] =
    {0,1,3,5,8,11,14,18,22,27,32,37,42,47,52,56,60,64,67,70,72,74,76,77};

// ======================= constexpr morlet coefficients ======================
__host__ __device__ constexpr double cabs_(double v) { return v < 0.0 ? -v : v; }

__host__ __device__ constexpr double cexp_(double xx) {
    if (xx < -120.0) return 0.0;
    const double LN2_HI = 6.93147180369123816490e-01;
    const double LN2_LO = 1.90821492927058770002e-10;
    const double INV_LN2 = 1.44269504088896338700e+00;
    double nd = xx * INV_LN2;
    int n = (int)(nd >= 0.0 ? nd + 0.5 : nd - 0.5);
    double r = (xx - (double)n * LN2_HI) - (double)n * LN2_LO;
    double term = 1.0, sum = 1.0;
    for (int i = 1; i <= 18; ++i) {
        term *= r / (double)i;
        sum += term;
        if (cabs_(term) < 1e-60) break;
    }
    double p = 1.0, b = (n < 0) ? 0.5 : 2.0;
    int m = (n < 0) ? -n : n;
    while (m) { if (m & 1) p *= b; m >>= 1; if (m) b *= b; }
    return sum * p;
}
__host__ __device__ constexpr double ccos_(double xx) {
    const double PIO2_1  = 1.57079632673412561417e+00;
    const double PIO2_1t = 6.07710050650619224932e-11;
    double ax = xx < 0.0 ? -xx : xx;
    int q = (int)(ax * 0.63661977236758134308 + 0.5);
    double r = (ax - (double)q * PIO2_1) - (double)q * PIO2_1t;
    double r2 = r * r;
    double cs = 1.0, tc = 1.0;
    for (int i = 1; i <= 10; ++i) {
        tc *= -r2 / (double)((2 * i - 1) * (2 * i));
        cs += tc;
        if (cabs_(tc) < 1e-60) break;
    }
    double sn = r, ts = r;
    for (int i = 1; i <= 10; ++i) {
        ts *= -r2 / (double)((2 * i) * (2 * i + 1));
        sn += ts;
        if (cabs_(ts) < 1e-60) break;
    }
    int quad = q & 3;
    return quad == 0 ? cs : quad == 1 ? -sn : quad == 2 ? -cs : sn;
}
__host__ __device__ constexpr double morlet_tap(int w, int p) {
    const double TWO_PI = 6.28318530717958647692;
    const double PI_M025 = 0.75112554446494248286;
    int N = 10 * w;
    double step = (2.0 * TWO_PI) / (double)(N - 1);
    double x = -TWO_PI + (double)p * step;
    double ew = cexp_(-0.5 * (double)(w * w));
    return (ccos_((double)w * x) - ew) * cexp_(-0.5 * x * x) * PI_M025;
}

__host__ __device__ constexpr unsigned short f2bf(double dv) {
    if (dv == 0.0) return 0;
    unsigned s = dv < 0.0 ? 1u : 0u;
    double x = s ? -dv : dv;
    int e = 127;
    while (x >= 2.0) { x *= 0.5; ++e; }
    while (x < 1.0)  { x *= 2.0; --e; }
    double mf = (x - 1.0) * 128.0;
    int m = (int)mf;
    double rem = mf - (double)m;
    if (rem > 0.5 || (rem == 0.5 && (m & 1))) ++m;
    if (m == 128) { m = 0; ++e; }
    if (e <= 0 || e >= 255) return (unsigned short)(s << 15);
    return (unsigned short)((s << 15) | ((unsigned)e << 7) | (unsigned)m);
}

__host__ __device__ constexpr double khat(int n, int p) {
    if (n >= NW) return 0.0;
    int w = n + 1;
    int q = p - 180 + 5 * w;
    if (q < 0 || q >= 10 * w) return 0.0;
    return morlet_tap(w, q);
}

struct BFt { unsigned v[BF_U32]; };
__host__ __device__ constexpr BFt make_bf() {
    BFt t{};
    for (int ks = 0; ks < KSTEPS; ++ks)
        for (int nt = NMIN[ks]; nt < NTB; ++nt) {
            int fi = FOFF[ks] + nt - NMIN[ks];
            for (int ln = 0; ln < 32; ++ln)
                for (int rg = 0; rg < 2; ++rg) {
                    int n  = nt * 8 + ln / 4;
                    int k0 = 16 * ks + (ln % 4) * 2 + rg * 8;
                    unsigned lo = f2bf(khat(n, k0));
                    unsigned hi = f2bf(khat(n, k0 + 1));
                    t.v[(fi * 32 + ln) * 2 + rg] = lo | (hi << 16);
                }
        }
    return t;
}
__device__ __align__(16) const BFt g_bf = make_bf();

// ============================ helpers =======================================
__device__ __forceinline__ void mma_bf16(float* d, unsigned a0, unsigned a1,
                                         unsigned a2, unsigned a3,
                                         unsigned b0, unsigned b1) {
    asm volatile(
        "mma.sync.aligned.m16n8k16.row.col.f32.bf16.bf16.f32 "
        "{%0,%1,%2,%3}, {%4,%5,%6,%7}, {%8,%9}, {%0,%1,%2,%3};"
        : "+f"(d[0]), "+f"(d[1]), "+f"(d[2]), "+f"(d[3])
        : "r"(a0), "r"(a1), "r"(a2), "r"(a3), "r"(b0), "r"(b1));
}

__device__ __forceinline__ float warp_sum(float v) {
    #pragma unroll
    for (int o = 16; o > 0; o >>= 1) v += __shfl_xor_sync(0xFFFFFFFFu, v, o);
    return v;
}

// ---------------------------------------------------------------------------
__global__ void __launch_bounds__(THREADS, 3)
cwt_mma_kernel(const float* __restrict__ o, const float* __restrict__ t,
               float* __restrict__ out) {
    __shared__ __align__(16) unsigned sBF[BF_U32];
    __shared__ __align__(16) unsigned sWI[WIN_A];
    __shared__ __align__(8) float sWin[WIN_A + 4];
    __shared__ float s_red[16];
    __shared__ unsigned s_last;
    __shared__ double s_fin[2 * THREADS];

    const int tid  = threadIdx.x;
    const int wid  = tid >> 5;              // 0..7
    const int lane = tid & 31;
    const int mbase = wid * 32;             // each warp: m32 (2 m-tiles)
    const int tile0 = blockIdx.x * STILE;

    // Compact B fragment table -> smem
    {
        const uint4* src = reinterpret_cast<const uint4*>(g_bf.v);
        uint4* dst = reinterpret_cast<uint4*>(sBF);
        for (int i = tid; i < BF_U32 / 4; i += THREADS) dst[i] = src[i];
    }

    // fp32 diff window, zero outside [0,L) and beyond WIN_V
    for (int j = tid; j < WIN_A + 4; j += THREADS) {
        int g = tile0 - 180 + j;
        float v = 0.f;
        if (j < WIN_V && g >= 0 && g < L_TOTAL) v = o[g] - t[g];
        sWin[j] = v;
    }
    __syncthreads();
    // packed bf16 pairs WI[j] = (d_j, d_{j+1}); fp32 wave |d| term
    for (int j = tid; j < WIN_A; j += THREADS) {
        unsigned lo = (unsigned)__bfloat16_as_ushort(__float2bfloat16(sWin[j]));
        unsigned hi = (unsigned)__bfloat16_as_ushort(__float2bfloat16(sWin[j + 1]));
        sWI[j] = lo | (hi << 16);
    }
    float wsum = fabsf(sWin[180 + tid]);    // outputs tile0 + tid, all valid
    __syncthreads();

    float acc[2][NTB][4];
    #pragma unroll
    for (int mt = 0; mt < 2; ++mt)
        #pragma unroll
        for (int nt = 0; nt < NTB; ++nt)
            #pragma unroll
            for (int r = 0; r < 4; ++r) acc[mt][nt][r] = 0.f;

    // Fully unrolled: per ks, only active n-tiles; each b-frag feeds 2 HMMAs
    #pragma unroll
    for (int ks = 0; ks < KSTEPS; ++ks) {
        const int bj = mbase + (lane >> 2) + 16 * ks + 2 * (lane & 3);
        unsigned p0 = sWI[bj];
        unsigned p1 = sWI[bj + 8];          // row+8 == col+8 (Hankel)
        unsigned p2 = sWI[bj + 16];
        unsigned p3 = sWI[bj + 24];
        unsigned p4 = sWI[bj + 32];
        #pragma unroll
        for (int nt = 0; nt < NTB; ++nt) {
            if (nt >= NMIN[ks]) {           // compile-time after unroll
                const int fi = FOFF[ks] + nt - NMIN[ks];
                uint2 b = *reinterpret_cast<const uint2*>(&sBF[fi * 64 + lane * 2]);
                mma_bf16(acc[0][nt], p0, p1, p1, p2, b.x, b.y);
                mma_bf16(acc[1][nt], p2, p3, p3, p4, b.x, b.y);
            }
        }
    }

    // |D| epilogue. Cols n = nt*8 + 2*(lane&3) + {0,1}; drop n >= 36.
    float csum = 0.f;
    #pragma unroll
    for (int mt = 0; mt < 2; ++mt) {
        #pragma unroll
        for (int nt = 0; nt < 4; ++nt)
            #pragma unroll
            for (int r = 0; r < 4; ++r) csum += fabsf(acc[mt][nt][r]);
        if ((lane & 3) < 2)
            #pragma unroll
            for (int r = 0; r < 4; ++r) csum += fabsf(acc[mt][4][r]);
    }

    // Block reduction -> per-block partials
    csum = warp_sum(csum);
    wsum = warp_sum(wsum);
    if (lane == 0) { s_red[wid] = csum; s_red[8 + wid] = wsum; }
    __syncthreads();
    if (tid == 0) {
        float c = 0.f, w = 0.f;
        #pragma unroll
        for (int i = 0; i < 8; ++i) { c += s_red[i]; w += s_red[8 + i]; }
        g_cwt_part[blockIdx.x]  = c;
        g_wave_part[blockIdx.x] = w;
    }

    // Last block finalizes
    __threadfence();
    if (tid == 0) {
        unsigned old = atomicAdd(&g_done, 1u);
        s_last = (old == GRID - 1) ? 1u : 0u;
    }
    __syncthreads();
    if (s_last) {
        double sc = 0.0, sw = 0.0;
        for (int i = tid; i < GRID; i += THREADS) {
            sc += (double)__ldcg(&g_cwt_part[i]);
            sw += (double)__ldcg(&g_wave_part[i]);
        }
        s_fin[tid] = sc; s_fin[THREADS + tid] = sw;
        __syncthreads();
        #pragma unroll
        for (int s = THREADS / 2; s > 0; s >>= 1) {
            if (tid < s) {
                s_fin[tid] += s_fin[tid + s];
                s_fin[THREADS + tid] += s_fin[THREADS + tid + s];
            }
            __syncthreads();
        }
        if (tid == 0) {
            double lw = s_fin[THREADS] / (double)L_TOTAL;
            double lc = s_fin[0] / (36.0 * (double)L_TOTAL);
            out[0] = (float)(0.5 * lw + 0.5 * lc);
            g_done = 0;                     // reset for next replay
        }
    }
}

extern "C" void kernel_launch(void* const* d_in, const int* in_sizes, int n_in,
                              void* d_out, int out_size) {
    const float* o = (const float*)d_in[0];
    const float* t = (const float*)d_in[1];
    float* out = (float*)d_out;

    cwt_mma_kernel<<<GRID, THREADS>>>(o, t, out);
}